// round 14
// baseline (speedup 1.0000x reference)
#include <cuda_runtime.h>

namespace {

constexpr int Wn    = 64;     // timesteps
constexpr int En    = 16;     // ensembles
constexpr int BIn   = 2560;   // B*I
constexpr int PROJn = 16;     // projection dim
constexpr int Fn    = 8;      // input features
constexpr int NSEQ  = En * BIn;      // 40960 independent sequences
constexpr int CHUNK = 4;             // timesteps per register chunk (R12 cadence)
constexpr int NCHUNK = Wn / CHUNK;   // 16
constexpr int TPB   = 128;           // grid = 320 (proven best)

__device__ __forceinline__ float tanh_hw(float x) {
    float y;
    asm("tanh.approx.f32 %0, %1;" : "=f"(y) : "f"(x));
    return y;
}

// Un-sinkable vectorized load (keeps prefetch distance honest).
__device__ __forceinline__ float4 ldg_v4(const float4* p) {
    float4 v;
    asm volatile("ld.global.v4.f32 {%0,%1,%2,%3}, [%4];"
                 : "=f"(v.x), "=f"(v.y), "=f"(v.z), "=f"(v.w)
                 : "l"(p));
    return v;
}

__global__ void __launch_bounds__(TPB, 2) gru_kernel(
    const float* __restrict__ x,      // (W, E, BI, F)
    const float* __restrict__ state,  // (1, E, BI, 1) -> NSEQ
    const float* __restrict__ wl,     // (E, PROJ, F)
    const float* __restrict__ bl,     // (E, PROJ)
    const float* __restrict__ wih,    // (E, 3, PROJ)
    const float* __restrict__ whh,    // (E, 3, 1)
    const float* __restrict__ bih,    // (E, 3)
    const float* __restrict__ bhh,    // (E, 3)
    float* __restrict__ out)          // (W, E, BI, 1)
{
    const int t = blockIdx.x * TPB + threadIdx.x;   // sequence id, exact grid
    const int e = t / BIn;

    // ---- Fold the two input matmuls into one (3 x 8) matrix per ensemble ----
    float C[3][8];
    float cb[3];
    #pragma unroll
    for (int g = 0; g < 3; ++g) {
        cb[g] = bih[e * 3 + g];
        #pragma unroll
        for (int f = 0; f < 8; ++f) C[g][f] = 0.0f;
    }
    const float4* wlv = reinterpret_cast<const float4*>(wl + (size_t)e * PROJn * Fn);
    #pragma unroll
    for (int p = 0; p < PROJn; ++p) {
        float4 wa = wlv[p * 2 + 0];
        float4 wb = wlv[p * 2 + 1];
        float blp = bl[e * PROJn + p];
        #pragma unroll
        for (int g = 0; g < 3; ++g) {
            float wg = wih[(e * 3 + g) * PROJn + p];
            cb[g] = fmaf(wg, blp, cb[g]);
            C[g][0] = fmaf(wg, wa.x, C[g][0]);
            C[g][1] = fmaf(wg, wa.y, C[g][1]);
            C[g][2] = fmaf(wg, wa.z, C[g][2]);
            C[g][3] = fmaf(wg, wa.w, C[g][3]);
            C[g][4] = fmaf(wg, wb.x, C[g][4]);
            C[g][5] = fmaf(wg, wb.y, C[g][5]);
            C[g][6] = fmaf(wg, wb.z, C[g][6]);
            C[g][7] = fmaf(wg, wb.w, C[g][7]);
        }
    }
    // Pre-fold sigmoid's x/2 into the r and z gate parameters:
    // sigmoid(x) = 0.5*tanh(x/2) + 0.5
    #pragma unroll
    for (int g = 0; g < 2; ++g) {
        cb[g] *= 0.5f;
        #pragma unroll
        for (int f = 0; f < 8; ++f) C[g][f] *= 0.5f;
    }
    const float whh0 = 0.5f * whh[e * 3 + 0], bhh0 = 0.5f * bhh[e * 3 + 0];
    const float whh1 = 0.5f * whh[e * 3 + 1], bhh1 = 0.5f * bhh[e * 3 + 1];
    const float whh2 = whh[e * 3 + 2],        bhh2 = bhh[e * 3 + 2];

    float h = state[t];

    const float4* xv = reinterpret_cast<const float4*>(x) + (size_t)t * 2;
    float* outp = out + t;

    float4 bufA[CHUNK][2];
    float4 bufB[CHUNK][2];
    float4 bufC[CHUNK][2];

    // One GRU step given the 8 input features of this timestep (R12-identical).
    auto gru_step = [&](int w, float4 a, float4 b) {
        float gi0 = cb[0], gi1 = cb[1], gi2 = cb[2];
        gi0 = fmaf(C[0][0], a.x, gi0); gi1 = fmaf(C[1][0], a.x, gi1); gi2 = fmaf(C[2][0], a.x, gi2);
        gi0 = fmaf(C[0][1], a.y, gi0); gi1 = fmaf(C[1][1], a.y, gi1); gi2 = fmaf(C[2][1], a.y, gi2);
        gi0 = fmaf(C[0][2], a.z, gi0); gi1 = fmaf(C[1][2], a.z, gi1); gi2 = fmaf(C[2][2], a.z, gi2);
        gi0 = fmaf(C[0][3], a.w, gi0); gi1 = fmaf(C[1][3], a.w, gi1); gi2 = fmaf(C[2][3], a.w, gi2);
        gi0 = fmaf(C[0][4], b.x, gi0); gi1 = fmaf(C[1][4], b.x, gi1); gi2 = fmaf(C[2][4], b.x, gi2);
        gi0 = fmaf(C[0][5], b.y, gi0); gi1 = fmaf(C[1][5], b.y, gi1); gi2 = fmaf(C[2][5], b.y, gi2);
        gi0 = fmaf(C[0][6], b.z, gi0); gi1 = fmaf(C[1][6], b.z, gi1); gi2 = fmaf(C[2][6], b.z, gi2);
        gi0 = fmaf(C[0][7], b.w, gi0); gi1 = fmaf(C[1][7], b.w, gi1); gi2 = fmaf(C[2][7], b.w, gi2);

        float gh0 = fmaf(whh0, h, bhh0);   // pre-halved
        float gh1 = fmaf(whh1, h, bhh1);   // pre-halved
        float gh2 = fmaf(whh2, h, bhh2);

        float r = fmaf(0.5f, tanh_hw(gi0 + gh0), 0.5f);   // sigmoid via HW tanh
        float z = fmaf(0.5f, tanh_hw(gi1 + gh1), 0.5f);
        float n = tanh_hw(fmaf(r, gh2, gi2));
        h = fmaf(z, h - n, n);                 // (1-z)*n + z*h
        outp[(size_t)w * NSEQ] = h;
    };

    auto load_chunk = [&](float4 (&dst)[CHUNK][2], int c) {
        #pragma unroll
        for (int s = 0; s < CHUNK; ++s) {
            size_t off = (size_t)(c * CHUNK + s) * (NSEQ * 2);
            dst[s][0] = ldg_v4(xv + off);       // volatile -> stays hoisted
            dst[s][1] = ldg_v4(xv + off + 1);
        }
    };

    auto compute_chunk = [&](float4 (&cur)[CHUNK][2], int c) {
        #pragma unroll
        for (int s = 0; s < CHUNK; ++s)
            gru_step(c * CHUNK + s, cur[s][0], cur[s][1]);
    };

    // Prime: chunks 0 and 1 in flight before any compute (depth 2).
    load_chunk(bufA, 0);
    load_chunk(bufB, 1);

    // Steady state: before computing chunk c, issue loads for chunk c+2.
    #pragma unroll
    for (int c = 0; c < NCHUNK; ++c) {
        const int ph = c % 3;
        if (ph == 0) {
            if (c + 2 < NCHUNK) load_chunk(bufC, c + 2);
            compute_chunk(bufA, c);
        } else if (ph == 1) {
            if (c + 2 < NCHUNK) load_chunk(bufA, c + 2);
            compute_chunk(bufB, c);
        } else {
            if (c + 2 < NCHUNK) load_chunk(bufB, c + 2);
            compute_chunk(bufC, c);
        }
    }
}

}  // namespace

extern "C" void kernel_launch(void* const* d_in, const int* in_sizes, int n_in,
                              void* d_out, int out_size) {
    (void)in_sizes; (void)n_in; (void)out_size;
    const float* x     = (const float*)d_in[0];
    const float* state = (const float*)d_in[1];
    const float* wl    = (const float*)d_in[2];
    const float* bl    = (const float*)d_in[3];
    const float* wih   = (const float*)d_in[4];
    const float* whh   = (const float*)d_in[5];
    const float* bih   = (const float*)d_in[6];
    const float* bhh   = (const float*)d_in[7];
    float* out = (float*)d_out;

    const int blocks = NSEQ / TPB;  // 40960 / 128 = 320, exact
    gru_kernel<<<blocks, TPB>>>(x, state, wl, bl, wih, whh, bih, bhh, out);
}

// round 15
// speedup vs baseline: 1.2569x; 1.2569x over previous
#include <cuda_runtime.h>

namespace {

constexpr int Wn    = 64;     // timesteps
constexpr int En    = 16;     // ensembles
constexpr int BIn   = 2560;   // B*I
constexpr int PROJn = 16;     // projection dim
constexpr int Fn    = 8;      // input features
constexpr int NSEQ  = En * BIn;      // 40960 independent sequences
constexpr int CHUNK = 4;             // timesteps per register chunk (R12 cadence)
constexpr int NCHUNK = Wn / CHUNK;   // 16
constexpr int TPB   = 128;           // grid = 320 (proven best)

__device__ __forceinline__ float tanh_hw(float x) {
    float y;
    asm("tanh.approx.f32 %0, %1;" : "=f"(y) : "f"(x));
    return y;
}

__global__ void __launch_bounds__(TPB, 3) gru_kernel(
    const float* __restrict__ x,      // (W, E, BI, F)
    const float* __restrict__ state,  // (1, E, BI, 1) -> NSEQ
    const float* __restrict__ wl,     // (E, PROJ, F)
    const float* __restrict__ bl,     // (E, PROJ)
    const float* __restrict__ wih,    // (E, 3, PROJ)
    const float* __restrict__ whh,    // (E, 3, 1)
    const float* __restrict__ bih,    // (E, 3)
    const float* __restrict__ bhh,    // (E, 3)
    float* __restrict__ out)          // (W, E, BI, 1)
{
    const int t = blockIdx.x * TPB + threadIdx.x;   // sequence id, exact grid
    const int e = t / BIn;

    // ---- Fold the two input matmuls into one (3 x 8) matrix per ensemble ----
    float C[3][8];
    float cb[3];
    #pragma unroll
    for (int g = 0; g < 3; ++g) {
        cb[g] = bih[e * 3 + g];
        #pragma unroll
        for (int f = 0; f < 8; ++f) C[g][f] = 0.0f;
    }
    const float4* wlv = reinterpret_cast<const float4*>(wl + (size_t)e * PROJn * Fn);
    #pragma unroll
    for (int p = 0; p < PROJn; ++p) {
        float4 wa = wlv[p * 2 + 0];
        float4 wb = wlv[p * 2 + 1];
        float blp = bl[e * PROJn + p];
        #pragma unroll
        for (int g = 0; g < 3; ++g) {
            float wg = wih[(e * 3 + g) * PROJn + p];
            cb[g] = fmaf(wg, blp, cb[g]);
            C[g][0] = fmaf(wg, wa.x, C[g][0]);
            C[g][1] = fmaf(wg, wa.y, C[g][1]);
            C[g][2] = fmaf(wg, wa.z, C[g][2]);
            C[g][3] = fmaf(wg, wa.w, C[g][3]);
            C[g][4] = fmaf(wg, wb.x, C[g][4]);
            C[g][5] = fmaf(wg, wb.y, C[g][5]);
            C[g][6] = fmaf(wg, wb.z, C[g][6]);
            C[g][7] = fmaf(wg, wb.w, C[g][7]);
        }
    }
    // Pre-fold sigmoid's x/2 into the r and z gate parameters:
    // sigmoid(x) = 0.5*tanh(x/2) + 0.5
    #pragma unroll
    for (int g = 0; g < 2; ++g) {
        cb[g] *= 0.5f;
        #pragma unroll
        for (int f = 0; f < 8; ++f) C[g][f] *= 0.5f;
    }
    const float whh0 = 0.5f * whh[e * 3 + 0], bhh0 = 0.5f * bhh[e * 3 + 0];
    const float whh1 = 0.5f * whh[e * 3 + 1], bhh1 = 0.5f * bhh[e * 3 + 1];
    const float whh2 = whh[e * 3 + 2],        bhh2 = bhh[e * 3 + 2];

    float h = state[t];

    const float4* xv = reinterpret_cast<const float4*>(x) + (size_t)t * 2;
    float* outp = out + t;

    float4 bufA[CHUNK][2];
    float4 bufB[CHUNK][2];
    float4 bufC[CHUNK][2];

    // One GRU step. r folded into n's argument:
    //   r = 0.5*tanh(u)+0.5 ; n_in = gi2 + r*gh2 = fma(0.5*gh2, tanh(u), gi2+0.5*gh2)
    auto gru_step = [&](int w, float4 a, float4 b) {
        float gi0 = cb[0], gi1 = cb[1], gi2 = cb[2];
        gi0 = fmaf(C[0][0], a.x, gi0); gi1 = fmaf(C[1][0], a.x, gi1); gi2 = fmaf(C[2][0], a.x, gi2);
        gi0 = fmaf(C[0][1], a.y, gi0); gi1 = fmaf(C[1][1], a.y, gi1); gi2 = fmaf(C[2][1], a.y, gi2);
        gi0 = fmaf(C[0][2], a.z, gi0); gi1 = fmaf(C[1][2], a.z, gi1); gi2 = fmaf(C[2][2], a.z, gi2);
        gi0 = fmaf(C[0][3], a.w, gi0); gi1 = fmaf(C[1][3], a.w, gi1); gi2 = fmaf(C[2][3], a.w, gi2);
        gi0 = fmaf(C[0][4], b.x, gi0); gi1 = fmaf(C[1][4], b.x, gi1); gi2 = fmaf(C[2][4], b.x, gi2);
        gi0 = fmaf(C[0][5], b.y, gi0); gi1 = fmaf(C[1][5], b.y, gi1); gi2 = fmaf(C[2][5], b.y, gi2);
        gi0 = fmaf(C[0][6], b.z, gi0); gi1 = fmaf(C[1][6], b.z, gi1); gi2 = fmaf(C[2][6], b.z, gi2);
        gi0 = fmaf(C[0][7], b.w, gi0); gi1 = fmaf(C[1][7], b.w, gi1); gi2 = fmaf(C[2][7], b.w, gi2);

        float gh0 = fmaf(whh0, h, bhh0);   // pre-halved
        float gh1 = fmaf(whh1, h, bhh1);   // pre-halved
        float gh2 = fmaf(whh2, h, bhh2);

        float tu = tanh_hw(gi0 + gh0);
        float tv = tanh_hw(gi1 + gh1);                // z's tanh, off critical path
        float b2 = 0.5f * gh2;
        float n  = tanh_hw(fmaf(b2, tu, gi2 + b2));
        float z  = fmaf(0.5f, tv, 0.5f);
        h = fmaf(z, h - n, n);                        // (1-z)*n + z*h
        outp[(size_t)w * NSEQ] = h;
    };

    auto load_chunk = [&](float4 (&dst)[CHUNK][2], int c) {
        #pragma unroll
        for (int s = 0; s < CHUNK; ++s) {
            size_t off = (size_t)(c * CHUNK + s) * (NSEQ * 2);
            dst[s][0] = xv[off];
            dst[s][1] = xv[off + 1];
        }
    };

    auto compute_chunk = [&](float4 (&cur)[CHUNK][2], int c) {
        #pragma unroll
        for (int s = 0; s < CHUNK; ++s)
            gru_step(c * CHUNK + s, cur[s][0], cur[s][1]);
    };

    // Prime: chunks 0 and 1 in flight before any compute (depth 2).
    load_chunk(bufA, 0);
    load_chunk(bufB, 1);

    // Steady state: before computing chunk c, issue loads for chunk c+2.
    #pragma unroll
    for (int c = 0; c < NCHUNK; ++c) {
        const int ph = c % 3;
        if (ph == 0) {
            if (c + 2 < NCHUNK) load_chunk(bufC, c + 2);
            compute_chunk(bufA, c);
        } else if (ph == 1) {
            if (c + 2 < NCHUNK) load_chunk(bufA, c + 2);
            compute_chunk(bufB, c);
        } else {
            if (c + 2 < NCHUNK) load_chunk(bufB, c + 2);
            compute_chunk(bufC, c);
        }
    }
}

}  // namespace

extern "C" void kernel_launch(void* const* d_in, const int* in_sizes, int n_in,
                              void* d_out, int out_size) {
    (void)in_sizes; (void)n_in; (void)out_size;
    const float* x     = (const float*)d_in[0];
    const float* state = (const float*)d_in[1];
    const float* wl    = (const float*)d_in[2];
    const float* bl    = (const float*)d_in[3];
    const float* wih   = (const float*)d_in[4];
    const float* whh   = (const float*)d_in[5];
    const float* bih   = (const float*)d_in[6];
    const float* bhh   = (const float*)d_in[7];
    float* out = (float*)d_out;

    const int blocks = NSEQ / TPB;  // 40960 / 128 = 320, exact
    gru_kernel<<<blocks, TPB>>>(x, state, wl, bl, wih, whh, bih, bhh, out);
}